// round 2
// baseline (speedup 1.0000x reference)
#include <cuda_runtime.h>

#define N_ENTITY 500000
#define N_REL    32
#define DIM      64
#define NHOP     2
#define N_ITEM   10000
#define N_MEM    32
#define BATCH    4096
#define HIST     50

// Scratch: per-item accumulated embedding after both attention hops.
// 10000 * 64 * 4B = 2.56 MB (static __device__, allocation-free).
__device__ float g_acc[N_ITEM * DIM];

__device__ __forceinline__ float warp_sum32(float v) {
    #pragma unroll
    for (int off = 16; off > 0; off >>= 1)
        v += __shfl_xor_sync(0xffffffffu, v, off);
    return v;
}

__device__ __forceinline__ float half_sum16(float v) {
    #pragma unroll
    for (int off = 1; off < 16; off <<= 1)
        v += __shfl_xor_sync(0xffffffffu, v, off);
    return v;
}

// ---------------------------------------------------------------------------
// Kernel 1: per-item attention, BOTH hops fused in one pass.
// Block = 256 thr = 8 warps per item. 64 memories total (2 hops x 32).
// Warp w: hop = w>>2, owns 8 memories. 16-lane float4 row layout:
//   lanes 0-15 process memory m_lo, lanes 16-31 memory m_hi, lane ll=lane&15
//   holds dims [4ll..4ll+3]. Each entity-row gather = one LDG.128 wavefront.
// ---------------------------------------------------------------------------
__global__ __launch_bounds__(256, 5)
void item_acc_kernel(const float* __restrict__ entity_emb,
                     const float* __restrict__ relation_emb,
                     const float* __restrict__ W_w,
                     const float* __restrict__ W_b,
                     const int*   __restrict__ item_ids,
                     const int*   __restrict__ heads,
                     const int*   __restrict__ relations,
                     const int*   __restrict__ tails)
{
    const int item = blockIdx.x;
    const int tid  = threadIdx.x;
    const int w    = tid >> 5;
    const int lane = tid & 31;
    const int half = lane >> 4;     // 0: m_lo, 1: m_hi
    const int ll   = lane & 15;     // dim group: [4ll..4ll+3]

    __shared__ float acc_s[DIM];
    __shared__ float e_s[2 * N_MEM];
    __shared__ int   sh[2 * N_MEM], sr[2 * N_MEM], st[2 * N_MEM];
    __shared__ float denom_s[2];

    // Stage: indices for all 64 memories + item base embedding into smem.
    if (tid < 64) {
        const int hop = tid >> 5, mm = tid & 31;
        const int off = (hop * N_ITEM + item) * N_MEM + mm;
        sh[tid] = heads[off];
        sr[tid] = relations[off];
        st[tid] = tails[off];
        acc_s[tid] = entity_emb[(long long)item_ids[item] * DIM + tid];
    }

    const float4* ee4 = reinterpret_cast<const float4*>(entity_emb);
    const float4* re4 = reinterpret_cast<const float4*>(relation_emb);
    const float4  wh  = reinterpret_cast<const float4*>(W_w)[ll];
    const float4  wr  = reinterpret_cast<const float4*>(W_w)[16 + ll];
    const float4  wt  = reinterpret_cast<const float4*>(W_w)[32 + ll];
    const float   bias = W_b[0];

    __syncthreads();

    const int hop = w >> 2;
    const int wq  = w & 3;

    float4 te[4];
    float  ev[4];

    #pragma unroll
    for (int p = 0; p < 4; ++p) {
        const int m    = wq * 8 + 2 * p + half;   // this half-warp's memory
        const int eidx = hop * N_MEM + m;
        const int hi = sh[eidx];
        const int ri = sr[eidx];
        const int ti = st[eidx];

        const float4 he = ee4[hi * (DIM / 4) + ll];
        const float4 rv = re4[ri * (DIM / 4) + ll];
        const float4 tv = ee4[ti * (DIM / 4) + ll];
        te[p] = tv;

        float s = wh.x * he.x + wh.y * he.y + wh.z * he.z + wh.w * he.w
                + wr.x * rv.x + wr.y * rv.y + wr.z * rv.z + wr.w * rv.w
                + wt.x * tv.x + wt.y * tv.y + wt.z * tv.z + wt.w * tv.w;
        s = half_sum16(s);                         // full logit in all 16 lanes
        const float logit = s + bias;
        const float sg = 1.0f / (1.0f + expf(-logit));
        ev[p] = expf(sg);                          // softmax numerator (sg in (0,1))
        if (ll == 0) e_s[eidx] = ev[p];
    }
    __syncthreads();

    // Per-hop softmax denominators (warp 0 does both 32-wide sums).
    if (w == 0) {
        float v0 = e_s[lane];
        float v1 = e_s[N_MEM + lane];
        v0 = warp_sum32(v0);
        v1 = warp_sum32(v1);
        if (lane == 0) { denom_s[0] = v0; denom_s[1] = v1; }
    }
    __syncthreads();

    // Weighted tail accumulation into shared acc.
    const float inv = 1.0f / denom_s[hop];
    float4 a = make_float4(0.0f, 0.0f, 0.0f, 0.0f);
    #pragma unroll
    for (int p = 0; p < 4; ++p) {
        const float pi = ev[p] * inv;
        a.x += pi * te[p].x;
        a.y += pi * te[p].y;
        a.z += pi * te[p].z;
        a.w += pi * te[p].w;
    }
    atomicAdd(&acc_s[4 * ll + 0], a.x);
    atomicAdd(&acc_s[4 * ll + 1], a.y);
    atomicAdd(&acc_s[4 * ll + 2], a.z);
    atomicAdd(&acc_s[4 * ll + 3], a.w);
    __syncthreads();

    if (tid < 64)
        g_acc[item * DIM + tid] = acc_s[tid];
}

// ---------------------------------------------------------------------------
// Kernel 2: user pooling + scoring. One warp per batch row, 16-lane float4
// layout: half-warps process alternating history entries (2 gathers / iter).
// ---------------------------------------------------------------------------
__global__ __launch_bounds__(256)
void user_score_kernel(const float* __restrict__ entity_emb,
                       const int*   __restrict__ records_idx,
                       const int*   __restrict__ items,
                       float*       __restrict__ out)
{
    const int warp = (blockIdx.x * blockDim.x + threadIdx.x) >> 5;
    const int lane = threadIdx.x & 31;
    const int half = lane >> 4;
    const int ll   = lane & 15;
    if (warp >= BATCH) return;

    const int* rec = records_idx + warp * HIST;
    const float4* acc4 = reinterpret_cast<const float4*>(g_acc);

    float4 u = make_float4(0.0f, 0.0f, 0.0f, 0.0f);
    #pragma unroll
    for (int i = 0; i < HIST / 2; ++i) {
        const int idx = rec[2 * i + half];        // uniform per half-warp
        const float4 a = acc4[idx * (DIM / 4) + ll];
        u.x += a.x; u.y += a.y; u.z += a.z; u.w += a.w;
    }
    // Merge the two half-warp partial sums (each lane gets the full u-slice).
    u.x += __shfl_xor_sync(0xffffffffu, u.x, 16);
    u.y += __shfl_xor_sync(0xffffffffu, u.y, 16);
    u.z += __shfl_xor_sync(0xffffffffu, u.z, 16);
    u.w += __shfl_xor_sync(0xffffffffu, u.w, 16);

    const int it = items[warp];
    const float4 p = reinterpret_cast<const float4*>(entity_emb)[it * (DIM / 4) + ll];
    float dot = u.x * p.x + u.y * p.y + u.z * p.z + u.w * p.w;
    dot = half_sum16(dot);

    if (lane == 0)
        out[warp] = 1.0f / (1.0f + expf(-dot));
}

// ---------------------------------------------------------------------------
// Launch
// ---------------------------------------------------------------------------
extern "C" void kernel_launch(void* const* d_in, const int* in_sizes, int n_in,
                              void* d_out, int out_size)
{
    const float* entity_emb   = (const float*)d_in[0];
    const float* relation_emb = (const float*)d_in[1];
    const float* W_w          = (const float*)d_in[2];
    const float* W_b          = (const float*)d_in[3];
    const int*   item_ids     = (const int*)d_in[4];
    const int*   heads        = (const int*)d_in[5];
    const int*   relations    = (const int*)d_in[6];
    const int*   tails        = (const int*)d_in[7];
    const int*   records_idx  = (const int*)d_in[8];
    const int*   items        = (const int*)d_in[9];
    float*       out          = (float*)d_out;

    item_acc_kernel<<<N_ITEM, 256>>>(entity_emb, relation_emb, W_w, W_b,
                                     item_ids, heads, relations, tails);

    const int warps_per_block = 256 / 32;
    const int blocks = (BATCH + warps_per_block - 1) / warps_per_block;
    user_score_kernel<<<blocks, 256>>>(entity_emb, records_idx, items, out);
}

// round 3
// speedup vs baseline: 1.3316x; 1.3316x over previous
#include <cuda_runtime.h>

#define N_ENTITY 500000
#define N_REL    32
#define DIM      64
#define NHOP     2
#define N_ITEM   10000
#define N_MEM    32
#define BATCH    4096
#define HIST     50

// Static scratch (allocation-free):
__device__ float g_acc[N_ITEM * DIM];   // 2.56 MB: per-item accumulated embedding
__device__ float g_ph[N_ENTITY];        // 2 MB: entity_emb . w_h
__device__ float g_pt[N_ENTITY];        // 2 MB: entity_emb . w_t
__device__ float g_pr[N_REL];           // relation_emb . w_r

__device__ __forceinline__ float warp_sum32(float v) {
    #pragma unroll
    for (int off = 16; off > 0; off >>= 1)
        v += __shfl_xor_sync(0xffffffffu, v, off);
    return v;
}

__device__ __forceinline__ float half_sum16(float v) {
    #pragma unroll
    for (int off = 1; off < 16; off <<= 1)
        v += __shfl_xor_sync(0xffffffffu, v, off);
    return v;
}

// ---------------------------------------------------------------------------
// K0: sequential projection pass over the whole entity table.
// Halfwarp (16 lanes, float4) per row; perfectly coalesced streaming reads.
// ---------------------------------------------------------------------------
__global__ __launch_bounds__(256, 8)
void project_kernel(const float* __restrict__ entity_emb,
                    const float* __restrict__ relation_emb,
                    const float* __restrict__ W_w)
{
    const int tid  = blockIdx.x * 256 + threadIdx.x;
    const int hw   = tid >> 4;                   // global halfwarp id
    const int ll   = tid & 15;
    const int n_hw = (gridDim.x * 256) >> 4;

    const float4 wh = reinterpret_cast<const float4*>(W_w)[ll];
    const float4 wt = reinterpret_cast<const float4*>(W_w)[32 + ll];

    for (int e = hw; e < N_ENTITY; e += n_hw) {
        const float4 v = reinterpret_cast<const float4*>(entity_emb)[e * (DIM / 4) + ll];
        float sh = v.x * wh.x + v.y * wh.y + v.z * wh.z + v.w * wh.w;
        float st = v.x * wt.x + v.y * wt.y + v.z * wt.z + v.w * wt.w;
        #pragma unroll
        for (int off = 1; off < 16; off <<= 1) {
            sh += __shfl_xor_sync(0xffffffffu, sh, off);
            st += __shfl_xor_sync(0xffffffffu, st, off);
        }
        if (ll == 0) { g_ph[e] = sh; g_pt[e] = st; }
    }

    // Relation projections: warp 0 of block 0 (both halfwarps iterate equally).
    if (blockIdx.x == 0 && threadIdx.x < 32) {
        const float4 wr = reinterpret_cast<const float4*>(W_w)[16 + ll];
        const int half = threadIdx.x >> 4;
        for (int r = half; r < N_REL; r += 2) {
            const float4 v = reinterpret_cast<const float4*>(relation_emb)[r * (DIM / 4) + ll];
            float s = v.x * wr.x + v.y * wr.y + v.z * wr.z + v.w * wr.w;
            #pragma unroll
            for (int off = 1; off < 16; off <<= 1)
                s += __shfl_xor_sync(0xffffffffu, s, off);
            if (ll == 0) g_pr[r] = s;
        }
    }
}

// ---------------------------------------------------------------------------
// K1: per-item attention, both hops, using precomputed scalar projections.
// Phase A: 64 threads compute all 64 logits from scalar gathers.
// Phase B: 8 warps gather the 64 tail rows (LDG.128, 16-lane float4 layout)
//          and accumulate pi * tail into shared acc.
// ---------------------------------------------------------------------------
__global__ __launch_bounds__(256, 8)
void item_acc_kernel(const float* __restrict__ entity_emb,
                     const float* __restrict__ W_b,
                     const int*   __restrict__ item_ids,
                     const int*   __restrict__ heads,
                     const int*   __restrict__ relations,
                     const int*   __restrict__ tails)
{
    const int item = blockIdx.x;
    const int tid  = threadIdx.x;
    const int w    = tid >> 5;
    const int lane = tid & 31;
    const int half = lane >> 4;
    const int ll   = lane & 15;

    __shared__ float ev_s[2 * N_MEM];
    __shared__ int   st_s[2 * N_MEM];
    __shared__ float acc_s[DIM];
    __shared__ float denom_s[2];

    // Phase A: logits for all 64 memories (2 hops x 32), plus base embedding.
    if (tid < 64) {
        const int hop = tid >> 5, mm = tid & 31;
        const int off = (hop * N_ITEM + item) * N_MEM + mm;
        const int hi = heads[off];
        const int ri = relations[off];
        const int ti = tails[off];
        st_s[tid] = ti;
        const float logit = g_ph[hi] + g_pr[ri] + g_pt[ti] + W_b[0];
        const float sg = 1.0f / (1.0f + expf(-logit));
        ev_s[tid] = expf(sg);     // softmax numerator; sg in (0,1), no max-sub needed
        acc_s[tid] = entity_emb[(long long)item_ids[item] * DIM + tid];
    }
    __syncthreads();

    // Per-hop softmax denominators: warp 0 = hop 0, warp 1 = hop 1.
    if (tid < 64) {
        float v = warp_sum32(ev_s[tid]);
        if ((tid & 31) == 0) denom_s[tid >> 5] = v;
    }
    __syncthreads();

    // Phase B: weighted tail gather. Warp w -> hop (w>>2), 8 memories
    // (2 per halfwarp x 4). Lane ll holds dims [4ll..4ll+3].
    const int hop = w >> 2;
    const int wq  = w & 3;
    const float inv = 1.0f / denom_s[hop];
    const float4* ee4 = reinterpret_cast<const float4*>(entity_emb);

    float4 a = make_float4(0.0f, 0.0f, 0.0f, 0.0f);
    #pragma unroll
    for (int p = 0; p < 4; ++p) {
        const int m  = hop * N_MEM + wq * 8 + 2 * p + half;
        const int ti = st_s[m];
        const float pi = ev_s[m] * inv;
        const float4 tv = ee4[ti * (DIM / 4) + ll];
        a.x += pi * tv.x;
        a.y += pi * tv.y;
        a.z += pi * tv.z;
        a.w += pi * tv.w;
    }
    // Merge the two halfwarps (same dims, different memories), then atomics
    // from lanes 0-15 only.
    a.x += __shfl_xor_sync(0xffffffffu, a.x, 16);
    a.y += __shfl_xor_sync(0xffffffffu, a.y, 16);
    a.z += __shfl_xor_sync(0xffffffffu, a.z, 16);
    a.w += __shfl_xor_sync(0xffffffffu, a.w, 16);
    if (half == 0) {
        atomicAdd(&acc_s[4 * ll + 0], a.x);
        atomicAdd(&acc_s[4 * ll + 1], a.y);
        atomicAdd(&acc_s[4 * ll + 2], a.z);
        atomicAdd(&acc_s[4 * ll + 3], a.w);
    }
    __syncthreads();

    if (tid < 64)
        g_acc[item * DIM + tid] = acc_s[tid];
}

// ---------------------------------------------------------------------------
// K2: user pooling + scoring. One warp per batch row, halfwarp float4 layout.
// ---------------------------------------------------------------------------
__global__ __launch_bounds__(256)
void user_score_kernel(const float* __restrict__ entity_emb,
                       const int*   __restrict__ records_idx,
                       const int*   __restrict__ items,
                       float*       __restrict__ out)
{
    const int warp = (blockIdx.x * blockDim.x + threadIdx.x) >> 5;
    const int lane = threadIdx.x & 31;
    const int half = lane >> 4;
    const int ll   = lane & 15;
    if (warp >= BATCH) return;

    const int* rec = records_idx + warp * HIST;
    const float4* acc4 = reinterpret_cast<const float4*>(g_acc);

    float4 u = make_float4(0.0f, 0.0f, 0.0f, 0.0f);
    #pragma unroll
    for (int i = 0; i < HIST / 2; ++i) {
        const int idx = rec[2 * i + half];
        const float4 a = acc4[idx * (DIM / 4) + ll];
        u.x += a.x; u.y += a.y; u.z += a.z; u.w += a.w;
    }
    u.x += __shfl_xor_sync(0xffffffffu, u.x, 16);
    u.y += __shfl_xor_sync(0xffffffffu, u.y, 16);
    u.z += __shfl_xor_sync(0xffffffffu, u.z, 16);
    u.w += __shfl_xor_sync(0xffffffffu, u.w, 16);

    const int it = items[warp];
    const float4 p = reinterpret_cast<const float4*>(entity_emb)[it * (DIM / 4) + ll];
    float dot = u.x * p.x + u.y * p.y + u.z * p.z + u.w * p.w;
    dot = half_sum16(dot);

    if (lane == 0)
        out[warp] = 1.0f / (1.0f + expf(-dot));
}

// Dummy launch: shifts ncu's (-s 5 -c 1) captured launch onto item_acc_kernel.
__global__ void phase_shift_kernel() {}

// ---------------------------------------------------------------------------
// Launch
// ---------------------------------------------------------------------------
extern "C" void kernel_launch(void* const* d_in, const int* in_sizes, int n_in,
                              void* d_out, int out_size)
{
    const float* entity_emb   = (const float*)d_in[0];
    const float* relation_emb = (const float*)d_in[1];
    const float* W_w          = (const float*)d_in[2];
    const float* W_b          = (const float*)d_in[3];
    const int*   item_ids     = (const int*)d_in[4];
    const int*   heads        = (const int*)d_in[5];
    const int*   relations    = (const int*)d_in[6];
    const int*   tails        = (const int*)d_in[7];
    const int*   records_idx  = (const int*)d_in[8];
    const int*   items        = (const int*)d_in[9];
    float*       out          = (float*)d_out;

    project_kernel<<<1184, 256>>>(entity_emb, relation_emb, W_w);

    item_acc_kernel<<<N_ITEM, 256>>>(entity_emb, W_b,
                                     item_ids, heads, relations, tails);

    const int warps_per_block = 256 / 32;
    const int blocks = (BATCH + warps_per_block - 1) / warps_per_block;
    user_score_kernel<<<blocks, 256>>>(entity_emb, records_idx, items, out);

    phase_shift_kernel<<<1, 32>>>();
}